// round 1
// baseline (speedup 1.0000x reference)
#include <cuda_runtime.h>
#include <cstdint>

#define BATCH 8192
#define IND   128
#define HID   1024
#define OUTD  128
#define NW    8          // warps per CTA
#define RPW   2          // batch rows per warp
#define RPC   (NW*RPW)   // 16 rows per CTA
#define NT    (HID/32)   // 32 hidden tiles of width 32

// smem layout (floats):
//   sh  : [NW][HID] float2   -> 16384 floats (s history, interleaved 2 rows)
//   ush : [NW][IND] float2   ->  2048 floats (u rows, interleaved)
//   bsT : [32][33]           ->  1056 floats (Bs chunk, transposed, padded)
//   stg : [128][33] / [32][129] -> 4224 floats (Bw / Ds / Dw staging)
#define SH_OFF   0
#define USH_OFF  16384
#define BST_OFF  18432
#define STG_OFF  19488
#define SMEM_FLOATS 23712
#define SMEM_BYTES  (SMEM_FLOATS * 4)

__device__ __forceinline__ float fast_tanh(float x) {
    // tanh(x) = 1 - 2/(exp(2x)+1), via ex2.approx + rcp.approx.
    // Absolute error ~1e-7 (safe for 1e-3 output tolerance, unlike tanh.approx).
    float e;
    asm("ex2.approx.f32 %0, %1;" : "=f"(e) : "f"(x * 2.8853900817779268f)); // 2*log2(e)
    float r;
    asm("rcp.approx.f32 %0, %1;" : "=f"(r) : "f"(e + 1.0f));
    return fmaf(-2.0f, r, 1.0f);
}

__global__ void __launch_bounds__(256, 2)
ren_kernel(const float* __restrict__ u,  const float* __restrict__ Bw,
           const float* __restrict__ Bs, const float* __restrict__ Ds,
           const float* __restrict__ Dw, float* __restrict__ out)
{
    extern __shared__ float smem[];
    float2* sh  = (float2*)(smem + SH_OFF);    // [NW][HID]
    float2* ush = (float2*)(smem + USH_OFF);   // [NW][IND]
    float*  bsT = smem + BST_OFF;              // [32][33]
    float*  stg = smem + STG_OFF;              // staging

    const int tid  = threadIdx.x;
    const int warp = tid >> 5;
    const int lane = tid & 31;
    const int r0   = blockIdx.x * RPC + warp * RPW;  // rows r0, r0+1

    // load this warp's 2 u rows into smem (interleaved float2)
    for (int k = lane; k < IND; k += 32)
        ush[warp*IND + k] = make_float2(u[(size_t)r0*IND + k], u[(size_t)(r0+1)*IND + k]);
    __syncwarp();

    float2*       mysh = sh  + warp*HID;
    const float2* myu  = ush + warp*IND;

    for (int t = 0; t < NT; ++t) {
        const int h0 = t * 32;

        // ---- stage BwT: stg[k*33 + c] = Bw[(h0+c)*IND + k], k in [0,128), c in [0,32)
        __syncthreads();
        {
            const int c  = tid >> 3;
            const int kb = (tid & 7) << 4;
            const float4* src = (const float4*)(Bw + (size_t)(h0 + c)*IND + kb);
            #pragma unroll
            for (int i = 0; i < 4; ++i) {
                float4 v = src[i];
                int k = kb + 4*i;
                stg[(k+0)*33 + c] = v.x;
                stg[(k+1)*33 + c] = v.y;
                stg[(k+2)*33 + c] = v.z;
                stg[(k+3)*33 + c] = v.w;
            }
        }
        __syncthreads();

        // ---- acc = (B u) for this tile, computed inline
        float accA = 0.f, accB = 0.f;
        #pragma unroll 8
        for (int k = 0; k < IND; ++k) {
            float2 uv = myu[k];
            float  w  = stg[k*33 + lane];
            accA = fmaf(uv.x, w, accA);
            accB = fmaf(uv.y, w, accB);
        }

        // ---- sweep over j-chunks: history GEMM chunks, then diagonal chunk
        for (int jc = 0; jc <= t; ++jc) {
            const int j0 = jc * 32;
            __syncthreads();
            {
                // stage bsT[j*33 + c] = Bs[(h0+c)*HID + j0 + j]
                const int c  = tid >> 3;
                const int jb = (tid & 7) << 2;
                float4 v = *(const float4*)(Bs + (size_t)(h0 + c)*HID + j0 + jb);
                bsT[(jb+0)*33 + c] = v.x;
                bsT[(jb+1)*33 + c] = v.y;
                bsT[(jb+2)*33 + c] = v.z;
                bsT[(jb+3)*33 + c] = v.w;
            }
            __syncthreads();

            if (jc < t) {
                // history: all j strictly below this tile -> full dense block
                #pragma unroll 8
                for (int j = 0; j < 32; ++j) {
                    float2 sv = mysh[j0 + j];
                    float  b  = bsT[j*33 + lane];
                    accA = fmaf(sv.x, b, accA);
                    accB = fmaf(sv.y, b, accB);
                }
            } else {
                // diagonal block: sequential sweep, strict lower triangular
                float sA = 0.f, sB = 0.f;
                #pragma unroll
                for (int i = 0; i < 32; ++i) {
                    float tA = fast_tanh(accA);
                    float tB = fast_tanh(accB);
                    float vA = __shfl_sync(0xffffffffu, tA, i);
                    float vB = __shfl_sync(0xffffffffu, tB, i);
                    float b  = bsT[i*33 + lane];
                    if (lane > i) {
                        accA = fmaf(b, vA, accA);
                        accB = fmaf(b, vB, accB);
                    }
                    if (lane == i) { sA = tA; sB = tB; }
                }
                mysh[h0 + lane] = make_float2(sA, sB);
            }
        }
    }

    // ---- output GEMM: y = s @ Ds^T + u @ Dw^T  (s never leaves SMEM)
    float oA[4] = {0.f,0.f,0.f,0.f};
    float oB[4] = {0.f,0.f,0.f,0.f};

    for (int jc = 0; jc < NT; ++jc) {
        const int j0 = jc * 32;
        __syncthreads();
        {
            // stage DsT: stg[j*129 + o] = Ds[o*HID + j0 + j], o in [0,128), j in [0,32)
            const int o  = tid >> 1;
            const int jb = (tid & 1) << 4;
            const float4* src = (const float4*)(Ds + (size_t)o*HID + j0 + jb);
            #pragma unroll
            for (int i = 0; i < 4; ++i) {
                float4 v = src[i];
                int j = jb + 4*i;
                stg[(j+0)*129 + o] = v.x;
                stg[(j+1)*129 + o] = v.y;
                stg[(j+2)*129 + o] = v.z;
                stg[(j+3)*129 + o] = v.w;
            }
        }
        __syncthreads();
        #pragma unroll 4
        for (int j = 0; j < 32; ++j) {
            float2 sv = mysh[j0 + j];
            #pragma unroll
            for (int g = 0; g < 4; ++g) {
                float d = stg[j*129 + lane + 32*g];
                oA[g] = fmaf(sv.x, d, oA[g]);
                oB[g] = fmaf(sv.y, d, oB[g]);
            }
        }
    }

    for (int kc = 0; kc < IND/32; ++kc) {
        const int k0 = kc * 32;
        __syncthreads();
        {
            const int o  = tid >> 1;
            const int jb = (tid & 1) << 4;
            const float4* src = (const float4*)(Dw + (size_t)o*IND + k0 + jb);
            #pragma unroll
            for (int i = 0; i < 4; ++i) {
                float4 v = src[i];
                int j = jb + 4*i;
                stg[(j+0)*129 + o] = v.x;
                stg[(j+1)*129 + o] = v.y;
                stg[(j+2)*129 + o] = v.z;
                stg[(j+3)*129 + o] = v.w;
            }
        }
        __syncthreads();
        #pragma unroll 4
        for (int k = 0; k < 32; ++k) {
            float2 uv = myu[k0 + k];
            #pragma unroll
            for (int g = 0; g < 4; ++g) {
                float d = stg[k*129 + lane + 32*g];
                oA[g] = fmaf(uv.x, d, oA[g]);
                oB[g] = fmaf(uv.y, d, oB[g]);
            }
        }
    }

    #pragma unroll
    for (int g = 0; g < 4; ++g) {
        out[(size_t)r0*OUTD     + lane + 32*g] = oA[g];
        out[(size_t)(r0+1)*OUTD + lane + 32*g] = oB[g];
    }
}

extern "C" void kernel_launch(void* const* d_in, const int* in_sizes, int n_in,
                              void* d_out, int out_size)
{
    const float* u  = (const float*)d_in[0];  // [8192,128]
    const float* Bw = (const float*)d_in[1];  // [1024,128]
    const float* Bs = (const float*)d_in[2];  // [1024,1024]
    const float* Ds = (const float*)d_in[3];  // [128,1024]
    const float* Dw = (const float*)d_in[4];  // [128,128]

    cudaFuncSetAttribute(ren_kernel,
                         cudaFuncAttributeMaxDynamicSharedMemorySize, SMEM_BYTES);
    ren_kernel<<<BATCH / RPC, 256, SMEM_BYTES>>>(u, Bw, Bs, Ds, Dw, (float*)d_out);
}